// round 2
// baseline (speedup 1.0000x reference)
#include <cuda_runtime.h>

// B=4, C=80, M=16 fixed by the reference; N derived at runtime (76725 @640x640).
#define BB 4
#define CC 80
#define C4 20            // float4 per anchor row
#define MM 16
#define TILE 64          // anchors per block
#define THREADS 256
#define MAXTILES 1280    // ceil(80000/64)

#define IMG_W 640.0f
#define IMG_H 640.0f
#define ALPHA_P 0.25f
#define ALPHA_N 0.75f
#define EPS_F 1e-4f
#define BETA_F (1.0f / 9.0f)

// Per-block partials + completion counter (no allocations allowed).
__device__ float        g_cls_part[BB * MAXTILES];
__device__ float        g_reg_part[BB * MAXTILES];
__device__ int          g_pos_part[BB * MAXTILES];
__device__ unsigned int g_count = 0;

__device__ __forceinline__ float block_reduce(float v, float* sred) {
    const int tid = threadIdx.x;
    sred[tid] = v;
    __syncthreads();
#pragma unroll
    for (int s = THREADS / 2; s > 0; s >>= 1) {
        if (tid < s) sred[tid] += sred[tid + s];
        __syncthreads();
    }
    const float r = sred[0];
    __syncthreads();
    return r;
}

__global__ void __launch_bounds__(THREADS)
retina_fused_kernel(const float* __restrict__ cls,
                    const float* __restrict__ regs,
                    const float* __restrict__ anchors,
                    const float* __restrict__ annots,
                    float* __restrict__ out,
                    int N, int numTiles) {
    const int b    = blockIdx.y;
    const int tile = blockIdx.x;
    const int n0   = tile * TILE;
    const int tid  = threadIdx.x;

    __shared__ float sann[MM * 5];
    __shared__ float slab[TILE];
    __shared__ float sred[THREADS];

    if (tid < MM * 5) sann[tid] = annots[b * MM * 5 + tid];
    __syncthreads();

    // ---- Phase 1: labels + reg loss for this tile (threads 0..63) ----
    float my_reg = 0.0f;
    float my_pos = 0.0f;
    if (tid < TILE) {
        const int n = n0 + tid;
        float label = -1.0f;
        if (n < N) {
            const long an = (long)b * N + n;
            const float4 a4 = reinterpret_cast<const float4*>(anchors)[an];
            const float a0 = a4.x, a1 = a4.y, a2 = a4.z, a3 = a4.w;
            const bool inside = (a0 > 0.0f) && (a1 > 0.0f) && (a2 < IMG_W) && (a3 < IMG_H);
            const float area_a = (a2 - a0) * (a3 - a1);

            float best = -1.0f;
            int   bidx = 0;
            bool  anyv = false;
#pragma unroll
            for (int j = 0; j < MM; j++) {
                const float g0 = sann[j * 5 + 0];
                const float g1 = sann[j * 5 + 1];
                const float g2 = sann[j * 5 + 2];
                const float g3 = sann[j * 5 + 3];
                const float gc = sann[j * 5 + 4];
                const bool valid = (gc >= 0.0f);
                anyv |= valid;
                const float area_g = (g2 - g0) * (g3 - g1);
                const float lx = fmaxf(a0, g0), ly = fmaxf(a1, g1);
                const float rx = fminf(a2, g2), ry = fminf(a3, g3);
                const float wx = fmaxf(rx - lx, 0.0f), wy = fmaxf(ry - ly, 0.0f);
                const float inter = wx * wy;
                float iou = inter / (area_a + area_g - inter);
                if (!valid) iou = -1.0f;
                if (iou > best) { best = iou; bidx = j; }   // first argmax on ties
            }

            if (best < 0.4f) label = 0.0f;
            if (best > 0.5f) label = sann[bidx * 5 + 4] + 1.0f;
            if (!anyv)   label = -1.0f;
            if (!inside) label = -1.0f;

            if (label > 0.0f) {
                const float g0 = sann[bidx * 5 + 0];
                const float g1 = sann[bidx * 5 + 1];
                const float g2 = sann[bidx * 5 + 2];
                const float g3 = sann[bidx * 5 + 3];
                const float aw = a2 - a0, ah = a3 - a1;
                const float acx = a0 + 0.5f * aw, acy = a1 + 0.5f * ah;
                const float gw = fmaxf(g2 - g0, 1.0f);
                const float gh = fmaxf(g3 - g1, 1.0f);
                const float gcx = g0 + 0.5f * gw, gcy = g1 + 0.5f * gh;
                const float t0 = ((gcx - acx) / aw) * 10.0f;
                const float t1 = ((gcy - acy) / ah) * 10.0f;
                const float t2 = __logf(gw / aw) * 5.0f;
                const float t3 = __logf(gh / ah) * 5.0f;

                const float4 r4 = reinterpret_cast<const float4*>(regs)[an];
                const float xs[4] = { fabsf(r4.x - t0), fabsf(r4.y - t1),
                                      fabsf(r4.z - t2), fabsf(r4.w - t3) };
#pragma unroll
                for (int k = 0; k < 4; k++) {
                    const float x = xs[k];
                    my_reg += (x < BETA_F) ? (0.5f * x * x / BETA_F) : (x - 0.5f * BETA_F);
                }
                my_pos = 1.0f;
            }
        }
        slab[tid] = label;
    }
    __syncthreads();

    // ---- Phase 2: focal loss, coalesced float4 sweep over the tile ----
    float acc = 0.0f;
    const float4* __restrict__ base =
        reinterpret_cast<const float4*>(cls) + (long)b * N * C4 + (long)n0 * C4;
    const int lim = min(TILE, N - n0) * C4;   // 1280 for full tiles
#pragma unroll 5
    for (int i = tid; i < lim; i += THREADS) {
        const int al = i / C4;
        const float label = slab[al];
        if (label < 0.0f) continue;
        const float4 p4 = base[i];
        const int c0 = (i - al * C4) * 4;
        const int lp = (int)label - 1;
        const float pv[4] = { p4.x, p4.y, p4.z, p4.w };
        float s = 0.0f;
#pragma unroll
        for (int k = 0; k < 4; k++) {
            const float p = fminf(fmaxf(pv[k], EPS_F), 1.0f - EPS_F);
            if ((c0 + k) == lp) {
                const float q = 1.0f - p;
                s += ALPHA_P * q * q * (-__logf(p));
            } else {
                s += ALPHA_N * p * p * (-__logf(1.0f - p));
            }
        }
        acc += s;
    }

    // ---- Phase 3: deterministic block reductions, write partials ----
    const float cls_sum = block_reduce(acc, sred);
    const float reg_sum = block_reduce(my_reg, sred);
    const float pos_sum = block_reduce(my_pos, sred);
    if (tid == 0) {
        const int pi = b * numTiles + tile;
        g_cls_part[pi] = cls_sum;
        g_reg_part[pi] = reg_sum;
        g_pos_part[pi] = (int)(pos_sum + 0.5f);
    }

    // ---- Phase 4: last block finalizes ----
    __shared__ bool is_last;
    __threadfence();
    if (tid == 0) {
        const unsigned total = gridDim.x * gridDim.y;
        is_last = (atomicAdd(&g_count, 1u) == total - 1u);
    }
    __syncthreads();
    if (!is_last) return;

    float cls_l = 0.0f, reg_l = 0.0f, nvalid = 0.0f;
    for (int bi = 0; bi < BB; bi++) {
        float c = 0.0f, r = 0.0f, p = 0.0f;
        for (int i = tid; i < numTiles; i += THREADS) {
            const int pi = bi * numTiles + i;
            c += g_cls_part[pi];
            r += g_reg_part[pi];
            p += (float)g_pos_part[pi];
        }
        c = block_reduce(c, sred);
        r = block_reduce(r, sred);
        p = block_reduce(p, sred);
        if (p > 0.0f) {
            cls_l += c / p;
            reg_l += r / (4.0f * p);
            nvalid += 1.0f;
        }
    }
    if (tid == 0) {
        nvalid = fmaxf(nvalid, 1.0f);
        out[0] = cls_l / nvalid;
        out[1] = reg_l / nvalid;
        g_count = 0;   // reset for next graph replay
    }
}

extern "C" void kernel_launch(void* const* d_in, const int* in_sizes, int n_in,
                              void* d_out, int out_size) {
    const float* cls     = (const float*)d_in[0];  // (B, N, C)
    const float* regs    = (const float*)d_in[1];  // (B, N, 4)
    const float* anchors = (const float*)d_in[2];  // (B, N, 4)
    const float* annots  = (const float*)d_in[3];  // (B, M, 5)

    const int N = in_sizes[1] / (BB * 4);
    const int numTiles = (N + TILE - 1) / TILE;

    dim3 grid(numTiles, BB);
    retina_fused_kernel<<<grid, THREADS>>>(cls, regs, anchors, annots,
                                           (float*)d_out, N, numTiles);
}

// round 3
// speedup vs baseline: 1.0159x; 1.0159x over previous
#include <cuda_runtime.h>

// B=4, C=80, M=16 fixed by the reference; N derived at runtime (76725 @640x640).
#define BB 4
#define CC 80
#define C4 20            // float4 per anchor row
#define MM 16
#define TILE 64          // anchors per block
#define THREADS 256      // 4 threads per anchor, 5 float4 each
#define MAXTILES 1280

#define IMG_W 640.0f
#define IMG_H 640.0f
#define EPS_F 1e-4f
#define BETA_F (1.0f / 9.0f)

__device__ float        g_cls_part[BB * MAXTILES];
__device__ float        g_reg_part[BB * MAXTILES];
__device__ int          g_pos_part[BB * MAXTILES];
__device__ unsigned int g_count = 0;

__device__ __forceinline__ float block_reduce(float v, float* sred) {
    const int tid = threadIdx.x;
    sred[tid] = v;
    __syncthreads();
#pragma unroll
    for (int s = THREADS / 2; s > 0; s >>= 1) {
        if (tid < s) sred[tid] += sred[tid + s];
        __syncthreads();
    }
    const float r = sred[0];
    __syncthreads();
    return r;
}

__global__ void __launch_bounds__(THREADS)
retina_fused_kernel(const float* __restrict__ cls,
                    const float* __restrict__ regs,
                    const float* __restrict__ anchors,
                    const float* __restrict__ annots,
                    float* __restrict__ out,
                    int N, int numTiles) {
    const int b    = blockIdx.y;
    const int tile = blockIdx.x;
    const int n0   = tile * TILE;
    const int tid  = threadIdx.x;

    __shared__ float sann[MM * 5];
    __shared__ float slab[TILE];
    __shared__ float sred[THREADS];

    if (tid < MM * 5) sann[tid] = annots[b * MM * 5 + tid];
    if (tid < TILE)   slab[tid] = -1.0f;
    __syncthreads();

    // ---- Phase 1 (threads 0..63): labels, reg loss, positive-class correction ----
    float my_reg = 0.0f;
    float my_pos = 0.0f;
    float my_cor = 0.0f;   // focal correction for this anchor's positive class
    if (tid < TILE) {
        const int n = n0 + tid;
        if (n < N) {
            const long an = (long)b * N + n;
            const float4 a4 = reinterpret_cast<const float4*>(anchors)[an];
            const float a0 = a4.x, a1 = a4.y, a2 = a4.z, a3 = a4.w;
            const bool inside = (a0 > 0.0f) && (a1 > 0.0f) && (a2 < IMG_W) && (a3 < IMG_H);
            const float area_a = (a2 - a0) * (a3 - a1);

            float best = -1.0f;
            int   bidx = 0;
            bool  anyv = false;
#pragma unroll
            for (int j = 0; j < MM; j++) {
                const float g0 = sann[j * 5 + 0];
                const float g1 = sann[j * 5 + 1];
                const float g2 = sann[j * 5 + 2];
                const float g3 = sann[j * 5 + 3];
                const float gc = sann[j * 5 + 4];
                const bool valid = (gc >= 0.0f);
                anyv |= valid;
                const float area_g = (g2 - g0) * (g3 - g1);
                const float lx = fmaxf(a0, g0), ly = fmaxf(a1, g1);
                const float rx = fminf(a2, g2), ry = fminf(a3, g3);
                const float wx = fmaxf(rx - lx, 0.0f), wy = fmaxf(ry - ly, 0.0f);
                const float inter = wx * wy;
                float iou = inter / (area_a + area_g - inter);
                if (!valid) iou = -1.0f;
                if (iou > best) { best = iou; bidx = j; }   // first argmax on ties
            }

            float label = -1.0f;
            if (best < 0.4f) label = 0.0f;
            if (best > 0.5f) label = sann[bidx * 5 + 4] + 1.0f;
            if (!anyv)   label = -1.0f;
            if (!inside) label = -1.0f;
            slab[tid] = label;

            if (label > 0.0f) {
                // smooth-L1 on regression targets
                const float g0 = sann[bidx * 5 + 0];
                const float g1 = sann[bidx * 5 + 1];
                const float g2 = sann[bidx * 5 + 2];
                const float g3 = sann[bidx * 5 + 3];
                const float aw = a2 - a0, ah = a3 - a1;
                const float acx = a0 + 0.5f * aw, acy = a1 + 0.5f * ah;
                const float gw = fmaxf(g2 - g0, 1.0f);
                const float gh = fmaxf(g3 - g1, 1.0f);
                const float gcx = g0 + 0.5f * gw, gcy = g1 + 0.5f * gh;
                const float t0 = ((gcx - acx) / aw) * 10.0f;
                const float t1 = ((gcy - acy) / ah) * 10.0f;
                const float t2 = __logf(gw / aw) * 5.0f;
                const float t3 = __logf(gh / ah) * 5.0f;

                const float4 r4 = reinterpret_cast<const float4*>(regs)[an];
                const float xs[4] = { fabsf(r4.x - t0), fabsf(r4.y - t1),
                                      fabsf(r4.z - t2), fabsf(r4.w - t3) };
#pragma unroll
                for (int k = 0; k < 4; k++) {
                    const float x = xs[k];
                    my_reg += (x < BETA_F) ? (0.5f * x * x / BETA_F) : (x - 0.5f * BETA_F);
                }
                my_pos = 1.0f;

                // focal correction at the positive class (one scalar load)
                const int lp = (int)label - 1;
                const float pv = cls[an * CC + lp];
                const float p = fminf(fmaxf(pv, EPS_F), 1.0f - EPS_F);
                const float q = 1.0f - p;
                my_cor = 0.25f * q * q * (-__logf(p)) - 0.75f * p * p * (-__logf(q));
            }
        }
    }
    __syncthreads();

    // ---- Phase 2: branchless negative-focal sweep ----
    // thread -> anchor tid>>2 (constant), float4 column (tid&3)+4*iter
    const int al     = tid >> 2;
    const int lane_c = tid & 3;
    const float label = slab[al];

    float acc = my_cor;
    if (label >= 0.0f) {
        const float4* __restrict__ base =
            reinterpret_cast<const float4*>(cls)
            + (long)b * N * C4 + (long)(n0 + al) * C4 + lane_c;
#pragma unroll
        for (int it = 0; it < 5; it++) {
            const float4 p4 = base[it * 4];
            const float pv[4] = { p4.x, p4.y, p4.z, p4.w };
#pragma unroll
            for (int k = 0; k < 4; k++) {
                // q = clamp(1-pv); p = 1-q (== clamped pv);  term = 0.75*p^2*(-log(q))
                const float q = fminf(fmaxf(1.0f - pv[k], EPS_F), 1.0f - EPS_F);
                const float p = 1.0f - q;
                acc -= 0.75f * p * p * __logf(q);
            }
        }
    }

    // ---- Phase 3: deterministic block reductions, write partials ----
    const float cls_sum = block_reduce(acc, sred);
    const float reg_sum = block_reduce(my_reg, sred);
    const float pos_sum = block_reduce(my_pos, sred);
    if (tid == 0) {
        const int pi = b * numTiles + tile;
        g_cls_part[pi] = cls_sum;
        g_reg_part[pi] = reg_sum;
        g_pos_part[pi] = (int)(pos_sum + 0.5f);
    }

    // ---- Phase 4: last block finalizes ----
    __shared__ bool is_last;
    __threadfence();
    if (tid == 0) {
        const unsigned total = gridDim.x * gridDim.y;
        is_last = (atomicAdd(&g_count, 1u) == total - 1u);
    }
    __syncthreads();
    if (!is_last) return;

    float cls_l = 0.0f, reg_l = 0.0f, nvalid = 0.0f;
    for (int bi = 0; bi < BB; bi++) {
        float c = 0.0f, r = 0.0f, p = 0.0f;
        for (int i = tid; i < numTiles; i += THREADS) {
            const int pi = bi * numTiles + i;
            c += g_cls_part[pi];
            r += g_reg_part[pi];
            p += (float)g_pos_part[pi];
        }
        c = block_reduce(c, sred);
        r = block_reduce(r, sred);
        p = block_reduce(p, sred);
        if (p > 0.0f) {
            cls_l += c / p;
            reg_l += r / (4.0f * p);
            nvalid += 1.0f;
        }
    }
    if (tid == 0) {
        nvalid = fmaxf(nvalid, 1.0f);
        out[0] = cls_l / nvalid;
        out[1] = reg_l / nvalid;
        g_count = 0;   // reset for next graph replay
    }
}

extern "C" void kernel_launch(void* const* d_in, const int* in_sizes, int n_in,
                              void* d_out, int out_size) {
    const float* cls     = (const float*)d_in[0];  // (B, N, C)
    const float* regs    = (const float*)d_in[1];  // (B, N, 4)
    const float* anchors = (const float*)d_in[2];  // (B, N, 4)
    const float* annots  = (const float*)d_in[3];  // (B, M, 5)

    const int N = in_sizes[1] / (BB * 4);
    const int numTiles = (N + TILE - 1) / TILE;

    dim3 grid(numTiles, BB);
    retina_fused_kernel<<<grid, THREADS>>>(cls, regs, anchors, annots,
                                           (float*)d_out, N, numTiles);
}

// round 4
// speedup vs baseline: 1.5741x; 1.5494x over previous
#include <cuda_runtime.h>

// B=4, C=80, M=16 fixed by the reference; N derived at runtime (76725 @640x640).
#define BB 4
#define CC 80
#define C4 20            // float4 per anchor row
#define MM 16
#define TILE 128         // anchors per block
#define HALF 64
#define THREADS 256      // 4 threads per anchor-quarter, 2 anchors per thread

#define IMG_W 640.0f
#define IMG_H 640.0f
#define EPS_F 1e-4f
#define BETA_F (1.0f / 9.0f)

__device__ float        g_cls_sum[BB];
__device__ float        g_reg_sum[BB];
__device__ int          g_pos[BB];
__device__ unsigned int g_count = 0;

__global__ void __launch_bounds__(THREADS, 3)
retina_fused_kernel(const float* __restrict__ cls,
                    const float* __restrict__ regs,
                    const float* __restrict__ anchors,
                    const float* __restrict__ annots,
                    float* __restrict__ out,
                    int N) {
    const int b    = blockIdx.y;
    const int n0   = blockIdx.x * TILE;
    const int tid  = threadIdx.x;

    __shared__ float sann[MM * 5];
    __shared__ float slab[TILE];
    __shared__ float swred[8][3];

    if (tid < MM * 5) sann[tid] = annots[b * MM * 5 + tid];
    if (tid < TILE)   slab[tid] = -1.0f;
    __syncthreads();

    // ---- Phase 1 (threads 0..127): label, reg loss, positive-class correction ----
    float my_reg = 0.0f;
    float my_pos = 0.0f;
    float my_cor = 0.0f;
    if (tid < TILE) {
        const int n = n0 + tid;
        if (n < N) {
            const long an = (long)b * N + n;
            const float4 a4 = reinterpret_cast<const float4*>(anchors)[an];
            const float a0 = a4.x, a1 = a4.y, a2 = a4.z, a3 = a4.w;
            const bool inside = (a0 > 0.0f) && (a1 > 0.0f) && (a2 < IMG_W) && (a3 < IMG_H);
            const float area_a = (a2 - a0) * (a3 - a1);

            float best = -1.0f;
            int   bidx = 0;
            bool  anyv = false;
#pragma unroll
            for (int j = 0; j < MM; j++) {
                const float g0 = sann[j * 5 + 0];
                const float g1 = sann[j * 5 + 1];
                const float g2 = sann[j * 5 + 2];
                const float g3 = sann[j * 5 + 3];
                const float gc = sann[j * 5 + 4];
                const bool valid = (gc >= 0.0f);
                anyv |= valid;
                const float area_g = (g2 - g0) * (g3 - g1);
                const float lx = fmaxf(a0, g0), ly = fmaxf(a1, g1);
                const float rx = fminf(a2, g2), ry = fminf(a3, g3);
                const float wx = fmaxf(rx - lx, 0.0f), wy = fmaxf(ry - ly, 0.0f);
                const float inter = wx * wy;
                float iou = inter / (area_a + area_g - inter);
                if (!valid) iou = -1.0f;
                if (iou > best) { best = iou; bidx = j; }   // first argmax on ties
            }

            float label = -1.0f;
            if (best < 0.4f) label = 0.0f;
            if (best > 0.5f) label = sann[bidx * 5 + 4] + 1.0f;
            if (!anyv)   label = -1.0f;
            if (!inside) label = -1.0f;
            slab[tid] = label;

            if (label > 0.0f) {
                const float g0 = sann[bidx * 5 + 0];
                const float g1 = sann[bidx * 5 + 1];
                const float g2 = sann[bidx * 5 + 2];
                const float g3 = sann[bidx * 5 + 3];
                const float aw = a2 - a0, ah = a3 - a1;
                const float acx = a0 + 0.5f * aw, acy = a1 + 0.5f * ah;
                const float gw = fmaxf(g2 - g0, 1.0f);
                const float gh = fmaxf(g3 - g1, 1.0f);
                const float gcx = g0 + 0.5f * gw, gcy = g1 + 0.5f * gh;
                const float t0 = ((gcx - acx) / aw) * 10.0f;
                const float t1 = ((gcy - acy) / ah) * 10.0f;
                const float t2 = __logf(gw / aw) * 5.0f;
                const float t3 = __logf(gh / ah) * 5.0f;

                const float4 r4 = reinterpret_cast<const float4*>(regs)[an];
                const float xs[4] = { fabsf(r4.x - t0), fabsf(r4.y - t1),
                                      fabsf(r4.z - t2), fabsf(r4.w - t3) };
#pragma unroll
                for (int k = 0; k < 4; k++) {
                    const float x = xs[k];
                    my_reg += (x < BETA_F) ? (0.5f * x * x / BETA_F) : (x - 0.5f * BETA_F);
                }
                my_pos = 1.0f;

                // focal correction at the positive class (sweep treats it as negative)
                const int lp = (int)label - 1;
                const float pv = cls[an * CC + lp];
                const float p = fminf(fmaxf(pv, EPS_F), 1.0f - EPS_F);
                const float q = 1.0f - p;
                my_cor = 0.25f * q * q * (-__logf(p)) - 0.75f * p * p * (-__logf(q));
            }
        }
    }
    __syncthreads();

    // ---- Phase 2: branchless negative-focal sweep, 10 front-batched LDG.128 ----
    const int al     = tid >> 2;          // first anchor within tile
    const int lane_c = tid & 3;
    const float lab0 = slab[al];
    const float lab1 = slab[al + HALF];
    const bool  u0 = (lab0 >= 0.0f);
    const bool  u1 = (lab1 >= 0.0f);

    const float4* __restrict__ base =
        reinterpret_cast<const float4*>(cls) + (long)b * N * C4 + (long)n0 * C4;
    const float4* __restrict__ b0 = base + al * C4 + lane_c;
    const float4* __restrict__ b1 = base + (al + HALF) * C4 + lane_c;

    float4 v0[5], v1[5];
    if (u0) {
#pragma unroll
        for (int it = 0; it < 5; it++) v0[it] = b0[it * 4];
    }
    if (u1) {
#pragma unroll
        for (int it = 0; it < 5; it++) v1[it] = b1[it * 4];
    }

    float acc = my_cor;
    if (u0) {
#pragma unroll
        for (int it = 0; it < 5; it++) {
            const float pv[4] = { v0[it].x, v0[it].y, v0[it].z, v0[it].w };
#pragma unroll
            for (int k = 0; k < 4; k++) {
                const float q = fminf(fmaxf(1.0f - pv[k], EPS_F), 1.0f - EPS_F);
                const float p = 1.0f - q;
                acc -= 0.75f * p * p * __logf(q);
            }
        }
    }
    if (u1) {
#pragma unroll
        for (int it = 0; it < 5; it++) {
            const float pv[4] = { v1[it].x, v1[it].y, v1[it].z, v1[it].w };
#pragma unroll
            for (int k = 0; k < 4; k++) {
                const float q = fminf(fmaxf(1.0f - pv[k], EPS_F), 1.0f - EPS_F);
                const float p = 1.0f - q;
                acc -= 0.75f * p * p * __logf(q);
            }
        }
    }

    // ---- Phase 3: warp shuffle reduce, one barrier, 3 atomics per block ----
#pragma unroll
    for (int o = 16; o; o >>= 1) {
        acc    += __shfl_down_sync(0xffffffffu, acc,    o);
        my_reg += __shfl_down_sync(0xffffffffu, my_reg, o);
        my_pos += __shfl_down_sync(0xffffffffu, my_pos, o);
    }
    const int wid = tid >> 5;
    if ((tid & 31) == 0) {
        swred[wid][0] = acc;
        swred[wid][1] = my_reg;
        swred[wid][2] = my_pos;
    }
    __syncthreads();
    if (tid == 0) {
        float c = 0.0f, r = 0.0f, p = 0.0f;
#pragma unroll
        for (int w = 0; w < 8; w++) {
            c += swred[w][0];
            r += swred[w][1];
            p += swred[w][2];
        }
        if (c != 0.0f) atomicAdd(&g_cls_sum[b], c);
        if (r != 0.0f) atomicAdd(&g_reg_sum[b], r);
        const int pi = (int)(p + 0.5f);
        if (pi) atomicAdd(&g_pos[b], pi);
    }

    // ---- Phase 4: last block finalizes + resets state for next replay ----
    __shared__ bool is_last;
    __threadfence();
    if (tid == 0) {
        const unsigned total = gridDim.x * gridDim.y;
        is_last = (atomicAdd(&g_count, 1u) == total - 1u);
    }
    __syncthreads();
    if (!is_last) return;

    if (tid == 0) {
        float cls_l = 0.0f, reg_l = 0.0f, nvalid = 0.0f;
#pragma unroll
        for (int bi = 0; bi < BB; bi++) {
            const float p = (float)g_pos[bi];
            if (p > 0.0f) {
                cls_l += g_cls_sum[bi] / p;
                reg_l += g_reg_sum[bi] / (4.0f * p);
                nvalid += 1.0f;
            }
            g_cls_sum[bi] = 0.0f;
            g_reg_sum[bi] = 0.0f;
            g_pos[bi] = 0;
        }
        nvalid = fmaxf(nvalid, 1.0f);
        out[0] = cls_l / nvalid;
        out[1] = reg_l / nvalid;
        g_count = 0;
    }
}

extern "C" void kernel_launch(void* const* d_in, const int* in_sizes, int n_in,
                              void* d_out, int out_size) {
    const float* cls     = (const float*)d_in[0];  // (B, N, C)
    const float* regs    = (const float*)d_in[1];  // (B, N, 4)
    const float* anchors = (const float*)d_in[2];  // (B, N, 4)
    const float* annots  = (const float*)d_in[3];  // (B, M, 5)

    const int N = in_sizes[1] / (BB * 4);
    const int numTiles = (N + TILE - 1) / TILE;

    dim3 grid(numTiles, BB);
    retina_fused_kernel<<<grid, THREADS>>>(cls, regs, anchors, annots,
                                           (float*)d_out, N);
}

// round 5
// speedup vs baseline: 1.9355x; 1.2296x over previous
#include <cuda_runtime.h>

// B=4, C=80, M=16 fixed by the reference; N derived at runtime (76725 @640x640).
#define BB 4
#define CC 80
#define C4 20            // float4 per anchor row
#define MM 16
#define TILE 256         // anchors per block (one per thread in phase 1)
#define THREADS 256      // phase 2: 4 threads/anchor, 4 anchors/thread in 2 waves

#define IMG_W 640.0f
#define IMG_H 640.0f
#define EPS_F 1e-4f
#define BETA_F (1.0f / 9.0f)
#define LN2_F 0.6931471805599453f

__device__ float        g_cls_sum[BB];
__device__ float        g_reg_sum[BB];
__device__ int          g_pos[BB];
__device__ unsigned int g_count = 0;

__global__ void __launch_bounds__(THREADS, 3)
retina_fused_kernel(const float* __restrict__ cls,
                    const float* __restrict__ regs,
                    const float* __restrict__ anchors,
                    const float* __restrict__ annots,
                    float* __restrict__ out,
                    int N) {
    const int b   = blockIdx.y;
    const int n0  = blockIdx.x * TILE;
    const int tid = threadIdx.x;

    __shared__ float sann[MM * 5];
    __shared__ float slab[TILE];
    __shared__ float swred[8][3];

    if (tid < MM * 5) sann[tid] = annots[b * MM * 5 + tid];
    __syncthreads();

    // ---- Phase 1 (all 256 threads, one anchor each) ----
    float my_reg = 0.0f;
    float my_pos = 0.0f;
    float my_cor = 0.0f;   // focal correction at the positive class
    {
        const int n = n0 + tid;
        float label = -1.0f;
        if (n < N) {
            const long an = (long)b * N + n;
            const float4 a4 = reinterpret_cast<const float4*>(anchors)[an];
            const float a0 = a4.x, a1 = a4.y, a2 = a4.z, a3 = a4.w;
            const bool inside = (a0 > 0.0f) && (a1 > 0.0f) && (a2 < IMG_W) && (a3 < IMG_H);
            const float area_a = (a2 - a0) * (a3 - a1);

            float best = -1.0f;
            int   bidx = 0;
            bool  anyv = false;
#pragma unroll
            for (int j = 0; j < MM; j++) {
                const float g0 = sann[j * 5 + 0];
                const float g1 = sann[j * 5 + 1];
                const float g2 = sann[j * 5 + 2];
                const float g3 = sann[j * 5 + 3];
                const float gc = sann[j * 5 + 4];
                const bool valid = (gc >= 0.0f);
                anyv |= valid;
                const float area_g = (g2 - g0) * (g3 - g1);
                const float lx = fmaxf(a0, g0), ly = fmaxf(a1, g1);
                const float rx = fminf(a2, g2), ry = fminf(a3, g3);
                const float wx = fmaxf(rx - lx, 0.0f), wy = fmaxf(ry - ly, 0.0f);
                const float inter = wx * wy;
                float iou = inter / (area_a + area_g - inter);
                if (!valid) iou = -1.0f;
                if (iou > best) { best = iou; bidx = j; }   // first argmax on ties
            }

            if (best < 0.4f) label = 0.0f;
            if (best > 0.5f) label = sann[bidx * 5 + 4] + 1.0f;
            if (!anyv)   label = -1.0f;
            if (!inside) label = -1.0f;

            if (label > 0.0f) {
                const float g0 = sann[bidx * 5 + 0];
                const float g1 = sann[bidx * 5 + 1];
                const float g2 = sann[bidx * 5 + 2];
                const float g3 = sann[bidx * 5 + 3];
                const float aw = a2 - a0, ah = a3 - a1;
                const float acx = a0 + 0.5f * aw, acy = a1 + 0.5f * ah;
                const float gw = fmaxf(g2 - g0, 1.0f);
                const float gh = fmaxf(g3 - g1, 1.0f);
                const float gcx = g0 + 0.5f * gw, gcy = g1 + 0.5f * gh;
                const float t0 = ((gcx - acx) / aw) * 10.0f;
                const float t1 = ((gcy - acy) / ah) * 10.0f;
                const float t2 = __logf(gw / aw) * 5.0f;
                const float t3 = __logf(gh / ah) * 5.0f;

                const float4 r4 = reinterpret_cast<const float4*>(regs)[an];
                const float xs[4] = { fabsf(r4.x - t0), fabsf(r4.y - t1),
                                      fabsf(r4.z - t2), fabsf(r4.w - t3) };
#pragma unroll
                for (int k = 0; k < 4; k++) {
                    const float x = xs[k];
                    my_reg += (x < BETA_F) ? (0.5f * x * x / BETA_F) : (x - 0.5f * BETA_F);
                }
                my_pos = 1.0f;

                // correction: true positive term minus what the sweep adds for this class
                const int lp = (int)label - 1;
                const float pv = cls[an * CC + lp];
                const float p = fminf(fmaxf(pv, EPS_F), 1.0f - EPS_F);
                const float q = 1.0f - p;
                my_cor = 0.25f * q * q * (-__logf(p)) - 0.75f * pv * pv * (-__logf(1.0f - pv));
            }
        }
        slab[tid] = label;
    }
    __syncthreads();

    // ---- Phase 2: negative-focal sweep; accumulate s = sum(pv^2 * lg2(1-pv)) ----
    const int al = tid >> 2;        // 0..63
    const int lc = tid & 3;
    const float4* __restrict__ base =
        reinterpret_cast<const float4*>(cls) + (long)b * N * C4 + (long)n0 * C4 + lc;

    float s = 0.0f;
#pragma unroll
    for (int w = 0; w < 2; w++) {
        const int a0 = al + w * 128;
        const int a1 = a0 + 64;
        const bool u0 = (slab[a0] >= 0.0f);
        const bool u1 = (slab[a1] >= 0.0f);
        const float4* __restrict__ p0 = base + a0 * C4;
        const float4* __restrict__ p1 = base + a1 * C4;

        float4 v0[5], v1[5];
        if (u0) {
#pragma unroll
            for (int it = 0; it < 5; it++) v0[it] = p0[it * 4];
        }
        if (u1) {
#pragma unroll
            for (int it = 0; it < 5; it++) v1[it] = p1[it * 4];
        }

        if (u0) {
#pragma unroll
            for (int it = 0; it < 5; it++) {
                const float pv[4] = { v0[it].x, v0[it].y, v0[it].z, v0[it].w };
#pragma unroll
                for (int k = 0; k < 4; k++)
                    s = fmaf(pv[k] * pv[k], __log2f(1.0f - pv[k]), s);
            }
        }
        if (u1) {
#pragma unroll
            for (int it = 0; it < 5; it++) {
                const float pv[4] = { v1[it].x, v1[it].y, v1[it].z, v1[it].w };
#pragma unroll
                for (int k = 0; k < 4; k++)
                    s = fmaf(pv[k] * pv[k], __log2f(1.0f - pv[k]), s);
            }
        }
    }
    // focal term: 0.75 * pv^2 * (-ln(1-pv)) = -0.75*ln2 * s
    float acc = fmaf(-0.75f * LN2_F, s, my_cor);

    // ---- Phase 3: warp shuffle reduce, one barrier, 3 atomics per block ----
#pragma unroll
    for (int o = 16; o; o >>= 1) {
        acc    += __shfl_down_sync(0xffffffffu, acc,    o);
        my_reg += __shfl_down_sync(0xffffffffu, my_reg, o);
        my_pos += __shfl_down_sync(0xffffffffu, my_pos, o);
    }
    const int wid = tid >> 5;
    if ((tid & 31) == 0) {
        swred[wid][0] = acc;
        swred[wid][1] = my_reg;
        swred[wid][2] = my_pos;
    }
    __syncthreads();
    if (tid == 0) {
        float c = 0.0f, r = 0.0f, p = 0.0f;
#pragma unroll
        for (int w = 0; w < 8; w++) {
            c += swred[w][0];
            r += swred[w][1];
            p += swred[w][2];
        }
        if (c != 0.0f) atomicAdd(&g_cls_sum[b], c);
        if (r != 0.0f) atomicAdd(&g_reg_sum[b], r);
        const int pi = (int)(p + 0.5f);
        if (pi) atomicAdd(&g_pos[b], pi);
    }

    // ---- Phase 4: last block finalizes + resets state for next replay ----
    __shared__ bool is_last;
    __threadfence();
    if (tid == 0) {
        const unsigned total = gridDim.x * gridDim.y;
        is_last = (atomicAdd(&g_count, 1u) == total - 1u);
    }
    __syncthreads();
    if (!is_last) return;

    if (tid == 0) {
        float cls_l = 0.0f, reg_l = 0.0f, nvalid = 0.0f;
#pragma unroll
        for (int bi = 0; bi < BB; bi++) {
            const float p = (float)g_pos[bi];
            if (p > 0.0f) {
                cls_l += g_cls_sum[bi] / p;
                reg_l += g_reg_sum[bi] / (4.0f * p);
                nvalid += 1.0f;
            }
            g_cls_sum[bi] = 0.0f;
            g_reg_sum[bi] = 0.0f;
            g_pos[bi] = 0;
        }
        nvalid = fmaxf(nvalid, 1.0f);
        out[0] = cls_l / nvalid;
        out[1] = reg_l / nvalid;
        g_count = 0;
    }
}

extern "C" void kernel_launch(void* const* d_in, const int* in_sizes, int n_in,
                              void* d_out, int out_size) {
    const float* cls     = (const float*)d_in[0];  // (B, N, C)
    const float* regs    = (const float*)d_in[1];  // (B, N, 4)
    const float* anchors = (const float*)d_in[2];  // (B, N, 4)
    const float* annots  = (const float*)d_in[3];  // (B, M, 5)

    const int N = in_sizes[1] / (BB * 4);
    const int numTiles = (N + TILE - 1) / TILE;

    dim3 grid(numTiles, BB);
    retina_fused_kernel<<<grid, THREADS>>>(cls, regs, anchors, annots,
                                           (float*)d_out, N);
}

// round 6
// speedup vs baseline: 2.8061x; 1.4498x over previous
#include <cuda_runtime.h>

// B=4, C=80, M=16 fixed by the reference; N derived at runtime (76725 @640x640).
#define BB 4
#define CC 80
#define C4 20            // float4 per anchor row
#define MM 16
#define TILE 256         // anchors per block (one per thread in phase 1)
#define THREADS 256

#define IMG_W 640.0f
#define IMG_H 640.0f
#define EPS_F 1e-4f
#define BETA_F (1.0f / 9.0f)
#define LN2_F 0.6931471805599453f

__device__ float        g_cls_sum[BB];
__device__ float        g_reg_sum[BB];
__device__ int          g_pos[BB];
__device__ unsigned int g_count = 0;

__global__ void __launch_bounds__(THREADS, 4)
retina_fused_kernel(const float* __restrict__ cls,
                    const float* __restrict__ regs,
                    const float* __restrict__ anchors,
                    const float* __restrict__ annots,
                    float* __restrict__ out,
                    int N) {
    const int b   = blockIdx.y;
    const int n0  = blockIdx.x * TILE;
    const int tid = threadIdx.x;

    __shared__ float sann[MM * 5];
    __shared__ float sarea[MM];      // per-GT area
    __shared__ float slab[TILE];
    __shared__ float swred[8][3];

    if (tid < MM * 5) sann[tid] = annots[b * MM * 5 + tid];
    __syncthreads();
    if (tid < MM) {
        sarea[tid] = (sann[tid * 5 + 2] - sann[tid * 5 + 0]) *
                     (sann[tid * 5 + 3] - sann[tid * 5 + 1]);
    }
    __syncthreads();

    // ---- Phase 1 (all 256 threads, one anchor each): division-free IoU argmax ----
    float my_reg = 0.0f;
    float my_pos = 0.0f;
    float my_cor = 0.0f;
    {
        const int n = n0 + tid;
        float label = -1.0f;
        if (n < N) {
            const long an = (long)b * N + n;
            const float4 a4 = reinterpret_cast<const float4*>(anchors)[an];
            const float a0 = a4.x, a1 = a4.y, a2 = a4.z, a3 = a4.w;
            const bool inside = (a0 > 0.0f) && (a1 > 0.0f) && (a2 < IMG_W) && (a3 < IMG_H);
            const float area_a = (a2 - a0) * (a3 - a1);

            // best IoU tracked as a positive-denominator fraction bnum/bden
            float bnum = -1.0f, bden = 1.0f;
            int   bidx = 0;
            bool  anyv = false;
#pragma unroll
            for (int j = 0; j < MM; j++) {
                const float g0 = sann[j * 5 + 0];
                const float g1 = sann[j * 5 + 1];
                const float g2 = sann[j * 5 + 2];
                const float g3 = sann[j * 5 + 3];
                const bool valid = (sann[j * 5 + 4] >= 0.0f);
                anyv |= valid;
                const float lx = fmaxf(a0, g0), ly = fmaxf(a1, g1);
                const float rx = fminf(a2, g2), ry = fminf(a3, g3);
                const float wx = fmaxf(rx - lx, 0.0f), wy = fmaxf(ry - ly, 0.0f);
                const float num = wx * wy;                       // inter >= 0
                const float den = area_a + sarea[j] - num;       // union > 0
                // iou_j > best  <=>  num*bden > bnum*den   (den,bden > 0)
                if (valid && (num * bden > bnum * den)) {
                    bnum = num; bden = den; bidx = j;
                }
            }

            // thresholds: iou < 0.4 <=> bnum < 0.4*bden ; iou > 0.5 <=> bnum > 0.5*bden
            if (bnum < 0.4f * bden) label = 0.0f;
            if (bnum > 0.5f * bden) label = sann[bidx * 5 + 4] + 1.0f;
            if (!anyv)   label = -1.0f;
            if (!inside) label = -1.0f;

            if (label > 0.0f) {
                const float g0 = sann[bidx * 5 + 0];
                const float g1 = sann[bidx * 5 + 1];
                const float g2 = sann[bidx * 5 + 2];
                const float g3 = sann[bidx * 5 + 3];
                const float aw = a2 - a0, ah = a3 - a1;
                const float acx = a0 + 0.5f * aw, acy = a1 + 0.5f * ah;
                const float gw = fmaxf(g2 - g0, 1.0f);
                const float gh = fmaxf(g3 - g1, 1.0f);
                const float gcx = g0 + 0.5f * gw, gcy = g1 + 0.5f * gh;
                const float t0 = ((gcx - acx) / aw) * 10.0f;
                const float t1 = ((gcy - acy) / ah) * 10.0f;
                const float t2 = __logf(gw / aw) * 5.0f;
                const float t3 = __logf(gh / ah) * 5.0f;

                const float4 r4 = reinterpret_cast<const float4*>(regs)[an];
                const float xs[4] = { fabsf(r4.x - t0), fabsf(r4.y - t1),
                                      fabsf(r4.z - t2), fabsf(r4.w - t3) };
#pragma unroll
                for (int k = 0; k < 4; k++) {
                    const float x = xs[k];
                    my_reg += (x < BETA_F) ? (0.5f * x * x / BETA_F) : (x - 0.5f * BETA_F);
                }
                my_pos = 1.0f;

                // correction: true positive focal term minus the negative term the sweep adds
                const int lp = (int)label - 1;
                const float pv = cls[an * CC + lp];
                const float p = fminf(fmaxf(pv, EPS_F), 1.0f - EPS_F);
                const float q = 1.0f - p;
                my_cor = 0.25f * q * q * (-__logf(p)) - 0.75f * pv * pv * (-__logf(1.0f - pv));
            }
        }
        slab[tid] = label;
    }
    __syncthreads();

    // ---- Phase 2: negative-focal sweep; s = sum(pv^2 * lg2(1-pv)), 2 waves of 10 LDG.128 ----
    const int al = tid >> 2;        // 0..63
    const int lc = tid & 3;
    const float4* __restrict__ base =
        reinterpret_cast<const float4*>(cls) + (long)b * N * C4 + (long)n0 * C4 + lc;

    float s = 0.0f;
#pragma unroll
    for (int w = 0; w < 2; w++) {
        const int a0 = al + w * 128;
        const int a1 = a0 + 64;
        const bool u0 = (slab[a0] >= 0.0f);
        const bool u1 = (slab[a1] >= 0.0f);
        const float4* __restrict__ p0 = base + a0 * C4;
        const float4* __restrict__ p1 = base + a1 * C4;

        float4 v0[5], v1[5];
        if (u0) {
#pragma unroll
            for (int it = 0; it < 5; it++) v0[it] = p0[it * 4];
        }
        if (u1) {
#pragma unroll
            for (int it = 0; it < 5; it++) v1[it] = p1[it * 4];
        }

        if (u0) {
#pragma unroll
            for (int it = 0; it < 5; it++) {
                const float pv[4] = { v0[it].x, v0[it].y, v0[it].z, v0[it].w };
#pragma unroll
                for (int k = 0; k < 4; k++)
                    s = fmaf(pv[k] * pv[k], __log2f(1.0f - pv[k]), s);
            }
        }
        if (u1) {
#pragma unroll
            for (int it = 0; it < 5; it++) {
                const float pv[4] = { v1[it].x, v1[it].y, v1[it].z, v1[it].w };
#pragma unroll
                for (int k = 0; k < 4; k++)
                    s = fmaf(pv[k] * pv[k], __log2f(1.0f - pv[k]), s);
            }
        }
    }
    // 0.75 * pv^2 * (-ln(1-pv)) summed == -0.75*ln2 * s
    float acc = fmaf(-0.75f * LN2_F, s, my_cor);

    // ---- Phase 3: warp shuffle reduce, one barrier, 3 atomics per block ----
#pragma unroll
    for (int o = 16; o; o >>= 1) {
        acc    += __shfl_down_sync(0xffffffffu, acc,    o);
        my_reg += __shfl_down_sync(0xffffffffu, my_reg, o);
        my_pos += __shfl_down_sync(0xffffffffu, my_pos, o);
    }
    const int wid = tid >> 5;
    if ((tid & 31) == 0) {
        swred[wid][0] = acc;
        swred[wid][1] = my_reg;
        swred[wid][2] = my_pos;
    }
    __syncthreads();
    if (tid == 0) {
        float c = 0.0f, r = 0.0f, p = 0.0f;
#pragma unroll
        for (int w = 0; w < 8; w++) {
            c += swred[w][0];
            r += swred[w][1];
            p += swred[w][2];
        }
        if (c != 0.0f) atomicAdd(&g_cls_sum[b], c);
        if (r != 0.0f) atomicAdd(&g_reg_sum[b], r);
        const int pi = (int)(p + 0.5f);
        if (pi) atomicAdd(&g_pos[b], pi);
    }

    // ---- Phase 4: last block finalizes + resets state for next replay ----
    __shared__ bool is_last;
    __threadfence();
    if (tid == 0) {
        const unsigned total = gridDim.x * gridDim.y;
        is_last = (atomicAdd(&g_count, 1u) == total - 1u);
    }
    __syncthreads();
    if (!is_last) return;

    if (tid == 0) {
        float cls_l = 0.0f, reg_l = 0.0f, nvalid = 0.0f;
#pragma unroll
        for (int bi = 0; bi < BB; bi++) {
            const float p = (float)g_pos[bi];
            if (p > 0.0f) {
                cls_l += g_cls_sum[bi] / p;
                reg_l += g_reg_sum[bi] / (4.0f * p);
                nvalid += 1.0f;
            }
            g_cls_sum[bi] = 0.0f;
            g_reg_sum[bi] = 0.0f;
            g_pos[bi] = 0;
        }
        nvalid = fmaxf(nvalid, 1.0f);
        out[0] = cls_l / nvalid;
        out[1] = reg_l / nvalid;
        g_count = 0;
    }
}

extern "C" void kernel_launch(void* const* d_in, const int* in_sizes, int n_in,
                              void* d_out, int out_size) {
    const float* cls     = (const float*)d_in[0];  // (B, N, C)
    const float* regs    = (const float*)d_in[1];  // (B, N, 4)
    const float* anchors = (const float*)d_in[2];  // (B, N, 4)
    const float* annots  = (const float*)d_in[3];  // (B, M, 5)

    const int N = in_sizes[1] / (BB * 4);
    const int numTiles = (N + TILE - 1) / TILE;

    dim3 grid(numTiles, BB);
    retina_fused_kernel<<<grid, THREADS>>>(cls, regs, anchors, annots,
                                           (float*)d_out, N);
}